// round 14
// baseline (speedup 1.0000x reference)
#include <cuda_runtime.h>
#include <cstdint>

#define Bb  8
#define Tt  2048
#define Cc  1024
#define HSd 64
#define Mrows (Bb*Tt)
#define NQT  16            // 128-row Q tiles per batch
#define MAXCH 4
#define PPITCH 40          // proj smem pitch (r6)

// Projected q/k/v (tf32-rounded fp32 bits)
__device__ float g_q[Mrows*HSd];
__device__ float g_k[Mrows*HSd];
__device__ float g_v[Mrows*HSd];
// Split-KV partials (128-row Q tiles)
__device__ float g_pO[Bb*NQT*MAXCH*128*64];
__device__ float g_pm[Bb*NQT*MAXCH*128];
__device__ float g_pl[Bb*NQT*MAXCH*128];
// Split-KV arrival counters (zeroed by proj each call)
__device__ int   g_cnt[Bb*NQT];

__device__ __forceinline__ uint32_t f2tf(float f) {
    uint32_t u;
    asm("cvt.rna.tf32.f32 %0, %1;" : "=r"(u) : "f"(f));
    return u;
}
__device__ __forceinline__ float tfv(float f) { return __uint_as_float(f2tf(f)); }
__device__ __forceinline__ float ex2(float x) {
    float r;
    asm("ex2.approx.ftz.f32 %0, %1;" : "=f"(r) : "f"(x));
    return r;
}
__device__ __forceinline__ void mma8(float* c, const uint32_t* a, uint32_t b0, uint32_t b1) {
    asm volatile(
        "mma.sync.aligned.m16n8k8.row.col.f32.tf32.tf32.f32 "
        "{%0,%1,%2,%3},{%4,%5,%6,%7},{%8,%9},{%0,%1,%2,%3};"
        : "+f"(c[0]), "+f"(c[1]), "+f"(c[2]), "+f"(c[3])
        : "r"(a[0]), "r"(a[1]), "r"(a[2]), "r"(a[3]), "r"(b0), "r"(b1));
}
__device__ __forceinline__ void cp16(uint32_t dst, const void* src) {
    asm volatile("cp.async.ca.shared.global [%0], [%1], 16;" :: "r"(dst), "l"(src));
}
#define CP_COMMIT() asm volatile("cp.async.commit_group;")
#define CP_WAIT0()  asm volatile("cp.async.wait_group 0;")

// ---------------------------------------------------------------------------
// Projection — r6 inner loop byte-identical; W rounding folded in (reads raw
// W, tfv applied in STWB at the same rounding point -> bit-identical g_wt
// values). Also zeroes the split-KV counters (CTA (0,0)) for the attn merge.
// ---------------------------------------------------------------------------
__global__ __launch_bounds__(128, 3)
void proj_kernel(const float* __restrict__ qv, const float* __restrict__ kv,
                 const float* __restrict__ vv,
                 const float* __restrict__ Wq, const float* __restrict__ Wk,
                 const float* __restrict__ Wv)
{
    extern __shared__ float sm[];
    float* As0 = sm;
    float* As1 = sm + 128*PPITCH;
    float* Ws0 = sm + 2*128*PPITCH;
    float* Ws1 = sm + 2*128*PPITCH + 32*72;

    const int tid  = threadIdx.x;

    if (blockIdx.x == 0 && blockIdx.y == 0 && tid < Bb*NQT)
        g_cnt[tid] = 0;

    const int m = blockIdx.y;
    const float* in  = (m == 0) ? qv : ((m == 1) ? kv : vv);
    float*       out = (m == 0) ? g_q : ((m == 1) ? g_k : g_v);
    const float* wt  = (m == 0) ? Wq : ((m == 1) ? Wk : Wv);

    const int wid  = tid >> 5;
    const int lane = tid & 31;
    const int g    = lane >> 2;
    const int tig  = lane & 3;
    const int row0 = blockIdx.x * 128;
    const int m0w  = wid * 32;

    const int aR = tid >> 2;
    const int aC = (tid & 3) * 8;
    const int wR = tid >> 2;
    const int wC = (tid & 3) * 16;

    float4 pa[8];
    float4 pw[4];

#define LDA(k0)                                                               \
    { _Pragma("unroll") for (int i = 0; i < 4; i++) {                         \
        const float* p = in + (size_t)(row0 + aR + 32*i)*Cc + (k0) + aC;      \
        pa[2*i]   = *(const float4*)p;                                        \
        pa[2*i+1] = *(const float4*)(p + 4); } }

#define LDWm(k0)                                                              \
    { const float* p = wt + (size_t)((k0) + wR)*HSd + wC;                     \
      _Pragma("unroll") for (int i = 0; i < 4; i++)                           \
          pw[i] = *(const float4*)(p + 4*i); }

#define STAB(buf)                                                             \
    { _Pragma("unroll") for (int i = 0; i < 4; i++) {                         \
        float4 a = pa[2*i], b = pa[2*i+1];                                    \
        *(float4*)&(buf)[(aR + 32*i)*PPITCH + aC] =                           \
            make_float4(tfv(a.x), tfv(b.x), tfv(a.y), tfv(b.y));              \
        *(float4*)&(buf)[(aR + 32*i)*PPITCH + aC + 4] =                       \
            make_float4(tfv(a.z), tfv(b.z), tfv(a.w), tfv(b.w)); } }

#define STWB(buf)                                                             \
    { _Pragma("unroll") for (int i = 0; i < 4; i++)                           \
        *(float4*)&(buf)[wR*72 + wC + 4*i] =                                  \
            make_float4(tfv(pw[i].x), tfv(pw[i].y), tfv(pw[i].z), tfv(pw[i].w)); }

    float acc[2][8][4];
#pragma unroll
    for (int mi = 0; mi < 2; mi++)
#pragma unroll
        for (int n = 0; n < 8; n++)
#pragma unroll
            for (int j = 0; j < 4; j++) acc[mi][n][j] = 0.f;

    LDA(0); LDWm(0);
    STAB(As0); STWB(Ws0);
    __syncthreads();

    for (int c = 0; c < 32; c++) {
        const int cur = c & 1;
        float* Acur = cur ? As1 : As0;
        float* Wcur = cur ? Ws1 : Ws0;
        float* Anxt = cur ? As0 : As1;
        float* Wnxt = cur ? Ws0 : Ws1;

        if (c < 31) { LDA(32*(c+1)); LDWm(32*(c+1)); }

#pragma unroll
        for (int ks = 0; ks < 4; ks++) {
            float2 a0 = *(const float2*)&Acur[(m0w + g     )*PPITCH + 8*ks + 2*tig];
            float2 a1 = *(const float2*)&Acur[(m0w + g +  8)*PPITCH + 8*ks + 2*tig];
            float2 a2 = *(const float2*)&Acur[(m0w + g + 16)*PPITCH + 8*ks + 2*tig];
            float2 a3 = *(const float2*)&Acur[(m0w + g + 24)*PPITCH + 8*ks + 2*tig];
            uint32_t af0[4] = { __float_as_uint(a0.x), __float_as_uint(a1.x),
                                __float_as_uint(a0.y), __float_as_uint(a1.y) };
            uint32_t af1[4] = { __float_as_uint(a2.x), __float_as_uint(a3.x),
                                __float_as_uint(a2.y), __float_as_uint(a3.y) };
#pragma unroll
            for (int n = 0; n < 8; n++) {
                uint32_t b0 = __float_as_uint(Wcur[(8*ks + tig    )*72 + 8*n + g]);
                uint32_t b1 = __float_as_uint(Wcur[(8*ks + tig + 4)*72 + 8*n + g]);
                mma8(acc[0][n], af0, b0, b1);
                mma8(acc[1][n], af1, b0, b1);
            }
        }
        if (c < 31) { STAB(Anxt); STWB(Wnxt); }
        __syncthreads();
    }

#pragma unroll
    for (int mi = 0; mi < 2; mi++) {
        const int rb = row0 + m0w + mi*16;
#pragma unroll
        for (int n = 0; n < 8; n++) {
            *(float2*)(out + (size_t)(rb + g    )*HSd + 8*n + 2*tig) =
                make_float2(tfv(acc[mi][n][0]), tfv(acc[mi][n][1]));
            *(float2*)(out + (size_t)(rb + g + 8)*HSd + 8*n + 2*tig) =
                make_float2(tfv(acc[mi][n][2]), tfv(acc[mi][n][3]));
        }
    }
#undef LDA
#undef LDWm
#undef STAB
#undef STWB
}

// ---------------------------------------------------------------------------
// Split-KV flash attention — r13 pipeline byte-identical; combine fused in:
// last-arriving chunk CTA for a (b,qb) merges all partials (same summation
// order as the old combine kernel -> bit-identical output).
// ---------------------------------------------------------------------------
__global__ __launch_bounds__(256, 2)
void attn_kernel(const int* __restrict__ mask, float* __restrict__ out)
{
    extern __shared__ float asm_[];
    float* Pb  = asm_;                        // 128*68
    float* Ks0 = asm_ + 128*68;               // 64*68
    float* Ks1 = Ks0 + 64*68;
    float* Vs0 = Ks1 + 64*68;                 // 64*72
    float* Vs1 = Vs0 + 64*72;
    int*   msk = (int*)(Vs1 + 64*72);         // [2][64]
    __shared__ int lastFlag;

    const int i = blockIdx.x;
    const int b = i & 7;
    const int r = 39 - (i >> 3);              // heavy (large qb) first
    int qb, chunk;
    if (r < 4)       { qb = r;                        chunk = 0; }
    else if (r < 12) { int t = r - 4;  qb = 4  + (t >> 1); chunk = t & 1; }
    else if (r < 24) { int t = r - 12; qb = 8  + t/3;      chunk = t - 3*(t/3); }
    else             { int t = r - 24; qb = 12 + (t >> 2); chunk = t & 3; }
    const int nch   = (2*qb + 9) >> 3;        // 1..4
    const int kb_lo = chunk * 8;
    const int kb_hi = min(kb_lo + 8, 2*qb + 2);

    const int q0   = qb * 128;
    const int tid  = threadIdx.x;
    const int wid  = tid >> 5;
    const int lane = tid & 31;
    const int g    = lane >> 2;
    const int tig  = lane & 3;
    const int m0w  = wid * 16;

#define ISSUE(kb, buf)                                                        \
    { const float* kg = g_k + (size_t)(b*Tt + (kb)*64)*HSd;                   \
      const float* vg = g_v + (size_t)(b*Tt + (kb)*64)*HSd;                   \
      float* kd = (buf) ? Ks1 : Ks0;                                          \
      float* vd = (buf) ? Vs1 : Vs0;                                          \
      _Pragma("unroll") for (int t4 = 0; t4 < 4; t4++) {                      \
          int t = tid + 256*t4;                                               \
          int rr = t >> 4, c4 = (t & 15) << 2;                                \
          cp16((uint32_t)__cvta_generic_to_shared(&kd[rr*68 + c4]),           \
               kg + rr*HSd + c4);                                             \
          cp16((uint32_t)__cvta_generic_to_shared(&vd[rr*72 + c4]),           \
               vg + rr*HSd + c4);                                             \
      }                                                                       \
      if (tid < 16)                                                           \
          cp16((uint32_t)__cvta_generic_to_shared(&msk[(buf)*64 + tid*4]),    \
               mask + b*Tt + (kb)*64 + tid*4);                                \
      CP_COMMIT(); }

    uint32_t qf[8][4];
    const float* qbase = g_q + (size_t)(b*Tt + q0 + m0w)*HSd;
#pragma unroll
    for (int k = 0; k < 8; k++) {
        qf[k][0] = __float_as_uint(qbase[(g    )*HSd + 8*k + tig    ]);
        qf[k][1] = __float_as_uint(qbase[(g + 8)*HSd + 8*k + tig    ]);
        qf[k][2] = __float_as_uint(qbase[(g    )*HSd + 8*k + tig + 4]);
        qf[k][3] = __float_as_uint(qbase[(g + 8)*HSd + 8*k + tig + 4]);
    }

    float o[8][4];
#pragma unroll
    for (int n = 0; n < 8; n++)
#pragma unroll
        for (int j = 0; j < 4; j++) o[n][j] = 0.f;
    float mr0 = -1e30f, mr1 = -1e30f, lr0 = 0.f, lr1 = 0.f;

    const float scale2 = 0.125f * 1.4426950408889634f;
    const int row0g = q0 + m0w + g;
    const int row1g = row0g + 8;

    ISSUE(kb_lo, 0);

    for (int kb = kb_lo; kb < kb_hi; kb++) {
        const int k0 = kb * 64;
        const int cur = (kb - kb_lo) & 1;
        const float* Kc = cur ? Ks1 : Ks0;
        const float* Vc = cur ? Vs1 : Vs0;
        const int*   mc = msk + cur*64;

        CP_WAIT0();
        __syncthreads();

        if (kb + 1 < kb_hi) ISSUE(kb + 1, cur ^ 1);

        // ---- S = Q K^T ----
        float s[8][4];
#pragma unroll
        for (int n = 0; n < 8; n++)
#pragma unroll
            for (int j = 0; j < 4; j++) s[n][j] = 0.f;
#pragma unroll
        for (int k = 0; k < 8; k++) {
#pragma unroll
            for (int n = 0; n < 8; n++) {
                uint32_t b0 = __float_as_uint(Kc[(8*n + g)*68 + 8*k + tig    ]);
                uint32_t b1 = __float_as_uint(Kc[(8*n + g)*68 + 8*k + tig + 4]);
                mma8(s[n], qf[k], b0, b1);
            }
        }

        // ---- scale (log2) + causal/pad mask ----
        const bool diag = (k0 >= q0);
#pragma unroll
        for (int n = 0; n < 8; n++) {
            int cl = 8*n + 2*tig;
            int2 mm = *(const int2*)&mc[cl];
            int c0 = k0 + cl, c1 = c0 + 1;
            bool v00 = (mm.x != 0) && (!diag || c0 <= row0g);
            bool v01 = (mm.y != 0) && (!diag || c1 <= row0g);
            bool v10 = (mm.x != 0) && (!diag || c0 <= row1g);
            bool v11 = (mm.y != 0) && (!diag || c1 <= row1g);
            s[n][0] = v00 ? s[n][0]*scale2 : -1e30f;
            s[n][1] = v01 ? s[n][1]*scale2 : -1e30f;
            s[n][2] = v10 ? s[n][2]*scale2 : -1e30f;
            s[n][3] = v11 ? s[n][3]*scale2 : -1e30f;
        }

        // ---- online softmax, base-2 ----
        {
            float m0 = -1e30f, m1 = -1e30f;
#pragma unroll
            for (int n = 0; n < 8; n++) {
                m0 = fmaxf(m0, fmaxf(s[n][0], s[n][1]));
                m1 = fmaxf(m1, fmaxf(s[n][2], s[n][3]));
            }
#pragma unroll
            for (int off = 1; off < 4; off <<= 1) {
                m0 = fmaxf(m0, __shfl_xor_sync(0xffffffffu, m0, off));
                m1 = fmaxf(m1, __shfl_xor_sync(0xffffffffu, m1, off));
            }
            float mn0 = fmaxf(mr0, m0), mn1 = fmaxf(mr1, m1);
            float al0 = ex2(mr0 - mn0), al1 = ex2(mr1 - mn1);
            float ls0 = 0.f, ls1 = 0.f;
#pragma unroll
            for (int n = 0; n < 8; n++) {
                s[n][0] = ex2(s[n][0] - mn0);
                s[n][1] = ex2(s[n][1] - mn0);
                s[n][2] = ex2(s[n][2] - mn1);
                s[n][3] = ex2(s[n][3] - mn1);
                ls0 += s[n][0] + s[n][1];
                ls1 += s[n][2] + s[n][3];
            }
#pragma unroll
            for (int off = 1; off < 4; off <<= 1) {
                ls0 += __shfl_xor_sync(0xffffffffu, ls0, off);
                ls1 += __shfl_xor_sync(0xffffffffu, ls1, off);
            }
            lr0 = lr0*al0 + ls0;  mr0 = mn0;
            lr1 = lr1*al1 + ls1;  mr1 = mn1;
#pragma unroll
            for (int n = 0; n < 8; n++) {
                o[n][0] *= al0; o[n][1] *= al0;
                o[n][2] *= al1; o[n][3] *= al1;
            }
        }

        // ---- P (tf32) into own rows of Pb; warp-private ----
#pragma unroll
        for (int n = 0; n < 8; n++) {
            float2 p0 = make_float2(tfv(s[n][0]), tfv(s[n][1]));
            float2 p1 = make_float2(tfv(s[n][2]), tfv(s[n][3]));
            *(float2*)&Pb[(m0w + g    )*68 + 8*n + 2*tig] = p0;
            *(float2*)&Pb[(m0w + g + 8)*68 + 8*n + 2*tig] = p1;
        }
        __syncwarp();

        // ---- O += P V ----
#pragma unroll
        for (int k = 0; k < 8; k++) {
            uint32_t af[4];
            af[0] = __float_as_uint(Pb[(m0w + g    )*68 + 8*k + tig    ]);
            af[1] = __float_as_uint(Pb[(m0w + g + 8)*68 + 8*k + tig    ]);
            af[2] = __float_as_uint(Pb[(m0w + g    )*68 + 8*k + tig + 4]);
            af[3] = __float_as_uint(Pb[(m0w + g + 8)*68 + 8*k + tig + 4]);
#pragma unroll
            for (int n = 0; n < 8; n++) {
                uint32_t b0 = __float_as_uint(Vc[(8*k + tig    )*72 + 8*n + g]);
                uint32_t b1 = __float_as_uint(Vc[(8*k + tig + 4)*72 + 8*n + g]);
                mma8(o[n], af, b0, b1);
            }
        }
    }

    // ---- epilogue ----
    if (nch == 1) {
        const float inv0 = 1.0f / lr0, inv1 = 1.0f / lr1;
        float* obase = out + (size_t)(b*Tt + q0 + m0w)*HSd;
#pragma unroll
        for (int n = 0; n < 8; n++) {
            *(float2*)(obase + (g    )*HSd + 8*n + 2*tig) =
                make_float2(o[n][0]*inv0, o[n][1]*inv0);
            *(float2*)(obase + (g + 8)*HSd + 8*n + 2*tig) =
                make_float2(o[n][2]*inv1, o[n][3]*inv1);
        }
    } else {
        const size_t idx = (size_t)((b*NQT + qb)*MAXCH + chunk);
        float* pO = g_pO + idx*8192;
#pragma unroll
        for (int n = 0; n < 8; n++) {
            *(float2*)&pO[(m0w + g    )*64 + 8*n + 2*tig] =
                make_float2(o[n][0], o[n][1]);
            *(float2*)&pO[(m0w + g + 8)*64 + 8*n + 2*tig] =
                make_float2(o[n][2], o[n][3]);
        }
        if (tig == 0) {
            g_pm[idx*128 + m0w + g    ] = mr0;
            g_pl[idx*128 + m0w + g    ] = lr0;
            g_pm[idx*128 + m0w + g + 8] = mr1;
            g_pl[idx*128 + m0w + g + 8] = lr1;
        }

        // ---- publish partial, last arriver merges (no spinning) ----
        __threadfence();
        __syncthreads();
        if (tid == 0) {
            int old = atomicAdd(&g_cnt[b*NQT + qb], 1);
            lastFlag = (old == nch - 1);
        }
        __syncthreads();

        if (lastFlag) {
            __threadfence();
            const int row  = tid >> 1;          // 0..127
            const int oc   = (tid & 1) * 32;    // 0 or 32
            const int base = (b*NQT + qb)*MAXCH;

            float mg = -1e30f;
            for (int ci = 0; ci < nch; ci++)
                mg = fmaxf(mg, g_pm[(base + ci)*128 + row]);

            float l = 0.f;
            float4 acc[8];
#pragma unroll
            for (int j = 0; j < 8; j++) acc[j] = make_float4(0.f, 0.f, 0.f, 0.f);

            for (int ci = 0; ci < nch; ci++) {
                float w = ex2(g_pm[(base + ci)*128 + row] - mg);
                l += w * g_pl[(base + ci)*128 + row];
                const float4* src =
                    (const float4*)&g_pO[(size_t)(base + ci)*8192 + row*64 + oc];
#pragma unroll
                for (int j = 0; j < 8; j++) {
                    float4 v = src[j];
                    acc[j].x += w*v.x; acc[j].y += w*v.y;
                    acc[j].z += w*v.z; acc[j].w += w*v.w;
                }
            }

            const float inv = 1.0f / l;
            float4* dst = (float4*)(out + (size_t)(b*Tt + q0 + row)*HSd + oc);
#pragma unroll
            for (int j = 0; j < 8; j++)
                dst[j] = make_float4(acc[j].x*inv, acc[j].y*inv,
                                     acc[j].z*inv, acc[j].w*inv);
        }
    }
#undef ISSUE
}

// ---------------------------------------------------------------------------
extern "C" void kernel_launch(void* const* d_in, const int* in_sizes, int n_in,
                              void* d_out, int out_size)
{
    const float* q_vec = (const float*)d_in[0];
    const float* k_vec = (const float*)d_in[1];
    const float* v_vec = (const float*)d_in[2];
    const int*   mask  = (const int*)  d_in[3];
    const float* Wq    = (const float*)d_in[4];
    const float* Wk    = (const float*)d_in[5];
    const float* Wv    = (const float*)d_in[6];
    float* out = (float*)d_out;

    const int proj_smem = (2*128*PPITCH + 2*32*72) * 4;               // 59392 B
    cudaFuncSetAttribute(proj_kernel,
                         cudaFuncAttributeMaxDynamicSharedMemorySize, proj_smem);
    const int attn_smem = (128*68 + 2*64*68 + 2*64*72) * 4 + 2*64*4;  // 107008 B
    cudaFuncSetAttribute(attn_kernel,
                         cudaFuncAttributeMaxDynamicSharedMemorySize, attn_smem);

    proj_kernel<<<dim3(Mrows/128, 3), 128, proj_smem>>>(q_vec, k_vec, v_vec,
                                                        Wq, Wk, Wv);
    attn_kernel<<<320, 256, attn_smem>>>(mask, out);
}

// round 15
// speedup vs baseline: 1.0658x; 1.0658x over previous
#include <cuda_runtime.h>
#include <cstdint>

#define Bb  8
#define Tt  2048
#define Cc  1024
#define HSd 64
#define Mrows (Bb*Tt)
#define NQT  16            // 128-row Q tiles per batch
#define MAXCH 4
#define PPITCH 40          // proj smem pitch (r6)

// Projected q/k/v (tf32-rounded fp32 bits)
__device__ float g_q[Mrows*HSd];
__device__ float g_k[Mrows*HSd];
__device__ float g_v[Mrows*HSd];
// Split-KV partials (128-row Q tiles)
__device__ float g_pO[Bb*NQT*MAXCH*128*64];
__device__ float g_pm[Bb*NQT*MAXCH*128];
__device__ float g_pl[Bb*NQT*MAXCH*128];

__device__ __forceinline__ uint32_t f2tf(float f) {
    uint32_t u;
    asm("cvt.rna.tf32.f32 %0, %1;" : "=r"(u) : "f"(f));
    return u;
}
__device__ __forceinline__ float tfv(float f) { return __uint_as_float(f2tf(f)); }
__device__ __forceinline__ float ex2(float x) {
    float r;
    asm("ex2.approx.ftz.f32 %0, %1;" : "=f"(r) : "f"(x));
    return r;
}
__device__ __forceinline__ void mma8(float* c, const uint32_t* a, uint32_t b0, uint32_t b1) {
    asm volatile(
        "mma.sync.aligned.m16n8k8.row.col.f32.tf32.tf32.f32 "
        "{%0,%1,%2,%3},{%4,%5,%6,%7},{%8,%9},{%0,%1,%2,%3};"
        : "+f"(c[0]), "+f"(c[1]), "+f"(c[2]), "+f"(c[3])
        : "r"(a[0]), "r"(a[1]), "r"(a[2]), "r"(a[3]), "r"(b0), "r"(b1));
}
__device__ __forceinline__ void cp16(uint32_t dst, const void* src) {
    asm volatile("cp.async.ca.shared.global [%0], [%1], 16;" :: "r"(dst), "l"(src));
}
#define CP_COMMIT() asm volatile("cp.async.commit_group;")
#define CP_WAIT0()  asm volatile("cp.async.wait_group 0;")

// ---------------------------------------------------------------------------
// Projection — r6 inner loop byte-identical; W tf32-rounding folded into the
// STWB staging (same rounding point as the old prep_w -> bit-identical).
// ---------------------------------------------------------------------------
__global__ __launch_bounds__(128, 3)
void proj_kernel(const float* __restrict__ qv, const float* __restrict__ kv,
                 const float* __restrict__ vv,
                 const float* __restrict__ Wq, const float* __restrict__ Wk,
                 const float* __restrict__ Wv)
{
    extern __shared__ float sm[];
    float* As0 = sm;
    float* As1 = sm + 128*PPITCH;
    float* Ws0 = sm + 2*128*PPITCH;
    float* Ws1 = sm + 2*128*PPITCH + 32*72;

    const int m = blockIdx.y;
    const float* in  = (m == 0) ? qv : ((m == 1) ? kv : vv);
    float*       out = (m == 0) ? g_q : ((m == 1) ? g_k : g_v);
    const float* wt  = (m == 0) ? Wq : ((m == 1) ? Wk : Wv);

    const int tid  = threadIdx.x;
    const int wid  = tid >> 5;
    const int lane = tid & 31;
    const int g    = lane >> 2;
    const int tig  = lane & 3;
    const int row0 = blockIdx.x * 128;
    const int m0w  = wid * 32;

    const int aR = tid >> 2;
    const int aC = (tid & 3) * 8;
    const int wR = tid >> 2;
    const int wC = (tid & 3) * 16;

    float4 pa[8];
    float4 pw[4];

#define LDA(k0)                                                               \
    { _Pragma("unroll") for (int i = 0; i < 4; i++) {                         \
        const float* p = in + (size_t)(row0 + aR + 32*i)*Cc + (k0) + aC;      \
        pa[2*i]   = *(const float4*)p;                                        \
        pa[2*i+1] = *(const float4*)(p + 4); } }

#define LDWm(k0)                                                              \
    { const float* p = wt + (size_t)((k0) + wR)*HSd + wC;                     \
      _Pragma("unroll") for (int i = 0; i < 4; i++)                           \
          pw[i] = *(const float4*)(p + 4*i); }

#define STAB(buf)                                                             \
    { _Pragma("unroll") for (int i = 0; i < 4; i++) {                         \
        float4 a = pa[2*i], b = pa[2*i+1];                                    \
        *(float4*)&(buf)[(aR + 32*i)*PPITCH + aC] =                           \
            make_float4(tfv(a.x), tfv(b.x), tfv(a.y), tfv(b.y));              \
        *(float4*)&(buf)[(aR + 32*i)*PPITCH + aC + 4] =                       \
            make_float4(tfv(a.z), tfv(b.z), tfv(a.w), tfv(b.w)); } }

#define STWB(buf)                                                             \
    { _Pragma("unroll") for (int i = 0; i < 4; i++)                           \
        *(float4*)&(buf)[wR*72 + wC + 4*i] =                                  \
            make_float4(tfv(pw[i].x), tfv(pw[i].y), tfv(pw[i].z), tfv(pw[i].w)); }

    float acc[2][8][4];
#pragma unroll
    for (int mi = 0; mi < 2; mi++)
#pragma unroll
        for (int n = 0; n < 8; n++)
#pragma unroll
            for (int j = 0; j < 4; j++) acc[mi][n][j] = 0.f;

    LDA(0); LDWm(0);
    STAB(As0); STWB(Ws0);
    __syncthreads();

    for (int c = 0; c < 32; c++) {
        const int cur = c & 1;
        float* Acur = cur ? As1 : As0;
        float* Wcur = cur ? Ws1 : Ws0;
        float* Anxt = cur ? As0 : As1;
        float* Wnxt = cur ? Ws0 : Ws1;

        if (c < 31) { LDA(32*(c+1)); LDWm(32*(c+1)); }

#pragma unroll
        for (int ks = 0; ks < 4; ks++) {
            float2 a0 = *(const float2*)&Acur[(m0w + g     )*PPITCH + 8*ks + 2*tig];
            float2 a1 = *(const float2*)&Acur[(m0w + g +  8)*PPITCH + 8*ks + 2*tig];
            float2 a2 = *(const float2*)&Acur[(m0w + g + 16)*PPITCH + 8*ks + 2*tig];
            float2 a3 = *(const float2*)&Acur[(m0w + g + 24)*PPITCH + 8*ks + 2*tig];
            uint32_t af0[4] = { __float_as_uint(a0.x), __float_as_uint(a1.x),
                                __float_as_uint(a0.y), __float_as_uint(a1.y) };
            uint32_t af1[4] = { __float_as_uint(a2.x), __float_as_uint(a3.x),
                                __float_as_uint(a2.y), __float_as_uint(a3.y) };
#pragma unroll
            for (int n = 0; n < 8; n++) {
                uint32_t b0 = __float_as_uint(Wcur[(8*ks + tig    )*72 + 8*n + g]);
                uint32_t b1 = __float_as_uint(Wcur[(8*ks + tig + 4)*72 + 8*n + g]);
                mma8(acc[0][n], af0, b0, b1);
                mma8(acc[1][n], af1, b0, b1);
            }
        }
        if (c < 31) { STAB(Anxt); STWB(Wnxt); }
        __syncthreads();
    }

#pragma unroll
    for (int mi = 0; mi < 2; mi++) {
        const int rb = row0 + m0w + mi*16;
#pragma unroll
        for (int n = 0; n < 8; n++) {
            *(float2*)(out + (size_t)(rb + g    )*HSd + 8*n + 2*tig) =
                make_float2(tfv(acc[mi][n][0]), tfv(acc[mi][n][1]));
            *(float2*)(out + (size_t)(rb + g + 8)*HSd + 8*n + 2*tig) =
                make_float2(tfv(acc[mi][n][2]), tfv(acc[mi][n][3]));
        }
    }
#undef LDA
#undef LDWm
#undef STAB
#undef STWB
}

// ---------------------------------------------------------------------------
// Split-KV flash attention — EXACT r13 version (best measured attn).
// ---------------------------------------------------------------------------
__global__ __launch_bounds__(256, 2)
void attn_kernel(const int* __restrict__ mask, float* __restrict__ out)
{
    extern __shared__ float asm_[];
    float* Pb  = asm_;                        // 128*68
    float* Ks0 = asm_ + 128*68;               // 64*68
    float* Ks1 = Ks0 + 64*68;
    float* Vs0 = Ks1 + 64*68;                 // 64*72
    float* Vs1 = Vs0 + 64*72;
    int*   msk = (int*)(Vs1 + 64*72);         // [2][64]

    const int i = blockIdx.x;
    const int b = i & 7;
    const int r = 39 - (i >> 3);              // heavy (large qb) first
    int qb, chunk;
    if (r < 4)       { qb = r;                        chunk = 0; }
    else if (r < 12) { int t = r - 4;  qb = 4  + (t >> 1); chunk = t & 1; }
    else if (r < 24) { int t = r - 12; qb = 8  + t/3;      chunk = t - 3*(t/3); }
    else             { int t = r - 24; qb = 12 + (t >> 2); chunk = t & 3; }
    const int nch   = (2*qb + 9) >> 3;        // 1..4
    const int kb_lo = chunk * 8;
    const int kb_hi = min(kb_lo + 8, 2*qb + 2);

    const int q0   = qb * 128;
    const int tid  = threadIdx.x;
    const int wid  = tid >> 5;
    const int lane = tid & 31;
    const int g    = lane >> 2;
    const int tig  = lane & 3;
    const int m0w  = wid * 16;

#define ISSUE(kb, buf)                                                        \
    { const float* kg = g_k + (size_t)(b*Tt + (kb)*64)*HSd;                   \
      const float* vg = g_v + (size_t)(b*Tt + (kb)*64)*HSd;                   \
      float* kd = (buf) ? Ks1 : Ks0;                                          \
      float* vd = (buf) ? Vs1 : Vs0;                                          \
      _Pragma("unroll") for (int t4 = 0; t4 < 4; t4++) {                      \
          int t = tid + 256*t4;                                               \
          int rr = t >> 4, c4 = (t & 15) << 2;                                \
          cp16((uint32_t)__cvta_generic_to_shared(&kd[rr*68 + c4]),           \
               kg + rr*HSd + c4);                                             \
          cp16((uint32_t)__cvta_generic_to_shared(&vd[rr*72 + c4]),           \
               vg + rr*HSd + c4);                                             \
      }                                                                       \
      if (tid < 16)                                                           \
          cp16((uint32_t)__cvta_generic_to_shared(&msk[(buf)*64 + tid*4]),    \
               mask + b*Tt + (kb)*64 + tid*4);                                \
      CP_COMMIT(); }

    uint32_t qf[8][4];
    const float* qbase = g_q + (size_t)(b*Tt + q0 + m0w)*HSd;
#pragma unroll
    for (int k = 0; k < 8; k++) {
        qf[k][0] = __float_as_uint(qbase[(g    )*HSd + 8*k + tig    ]);
        qf[k][1] = __float_as_uint(qbase[(g + 8)*HSd + 8*k + tig    ]);
        qf[k][2] = __float_as_uint(qbase[(g    )*HSd + 8*k + tig + 4]);
        qf[k][3] = __float_as_uint(qbase[(g + 8)*HSd + 8*k + tig + 4]);
    }

    float o[8][4];
#pragma unroll
    for (int n = 0; n < 8; n++)
#pragma unroll
        for (int j = 0; j < 4; j++) o[n][j] = 0.f;
    float mr0 = -1e30f, mr1 = -1e30f, lr0 = 0.f, lr1 = 0.f;

    const float scale2 = 0.125f * 1.4426950408889634f;
    const int row0g = q0 + m0w + g;
    const int row1g = row0g + 8;

    ISSUE(kb_lo, 0);

    for (int kb = kb_lo; kb < kb_hi; kb++) {
        const int k0 = kb * 64;
        const int cur = (kb - kb_lo) & 1;
        const float* Kc = cur ? Ks1 : Ks0;
        const float* Vc = cur ? Vs1 : Vs0;
        const int*   mc = msk + cur*64;

        CP_WAIT0();
        __syncthreads();

        if (kb + 1 < kb_hi) ISSUE(kb + 1, cur ^ 1);

        // ---- S = Q K^T ----
        float s[8][4];
#pragma unroll
        for (int n = 0; n < 8; n++)
#pragma unroll
            for (int j = 0; j < 4; j++) s[n][j] = 0.f;
#pragma unroll
        for (int k = 0; k < 8; k++) {
#pragma unroll
            for (int n = 0; n < 8; n++) {
                uint32_t b0 = __float_as_uint(Kc[(8*n + g)*68 + 8*k + tig    ]);
                uint32_t b1 = __float_as_uint(Kc[(8*n + g)*68 + 8*k + tig + 4]);
                mma8(s[n], qf[k], b0, b1);
            }
        }

        // ---- scale (log2) + causal/pad mask ----
        const bool diag = (k0 >= q0);
#pragma unroll
        for (int n = 0; n < 8; n++) {
            int cl = 8*n + 2*tig;
            int2 mm = *(const int2*)&mc[cl];
            int c0 = k0 + cl, c1 = c0 + 1;
            bool v00 = (mm.x != 0) && (!diag || c0 <= row0g);
            bool v01 = (mm.y != 0) && (!diag || c1 <= row0g);
            bool v10 = (mm.x != 0) && (!diag || c0 <= row1g);
            bool v11 = (mm.y != 0) && (!diag || c1 <= row1g);
            s[n][0] = v00 ? s[n][0]*scale2 : -1e30f;
            s[n][1] = v01 ? s[n][1]*scale2 : -1e30f;
            s[n][2] = v10 ? s[n][2]*scale2 : -1e30f;
            s[n][3] = v11 ? s[n][3]*scale2 : -1e30f;
        }

        // ---- online softmax, base-2 ----
        {
            float m0 = -1e30f, m1 = -1e30f;
#pragma unroll
            for (int n = 0; n < 8; n++) {
                m0 = fmaxf(m0, fmaxf(s[n][0], s[n][1]));
                m1 = fmaxf(m1, fmaxf(s[n][2], s[n][3]));
            }
#pragma unroll
            for (int off = 1; off < 4; off <<= 1) {
                m0 = fmaxf(m0, __shfl_xor_sync(0xffffffffu, m0, off));
                m1 = fmaxf(m1, __shfl_xor_sync(0xffffffffu, m1, off));
            }
            float mn0 = fmaxf(mr0, m0), mn1 = fmaxf(mr1, m1);
            float al0 = ex2(mr0 - mn0), al1 = ex2(mr1 - mn1);
            float ls0 = 0.f, ls1 = 0.f;
#pragma unroll
            for (int n = 0; n < 8; n++) {
                s[n][0] = ex2(s[n][0] - mn0);
                s[n][1] = ex2(s[n][1] - mn0);
                s[n][2] = ex2(s[n][2] - mn1);
                s[n][3] = ex2(s[n][3] - mn1);
                ls0 += s[n][0] + s[n][1];
                ls1 += s[n][2] + s[n][3];
            }
#pragma unroll
            for (int off = 1; off < 4; off <<= 1) {
                ls0 += __shfl_xor_sync(0xffffffffu, ls0, off);
                ls1 += __shfl_xor_sync(0xffffffffu, ls1, off);
            }
            lr0 = lr0*al0 + ls0;  mr0 = mn0;
            lr1 = lr1*al1 + ls1;  mr1 = mn1;
#pragma unroll
            for (int n = 0; n < 8; n++) {
                o[n][0] *= al0; o[n][1] *= al0;
                o[n][2] *= al1; o[n][3] *= al1;
            }
        }

        // ---- P (tf32) into own rows of Pb; warp-private ----
#pragma unroll
        for (int n = 0; n < 8; n++) {
            float2 p0 = make_float2(tfv(s[n][0]), tfv(s[n][1]));
            float2 p1 = make_float2(tfv(s[n][2]), tfv(s[n][3]));
            *(float2*)&Pb[(m0w + g    )*68 + 8*n + 2*tig] = p0;
            *(float2*)&Pb[(m0w + g + 8)*68 + 8*n + 2*tig] = p1;
        }
        __syncwarp();

        // ---- O += P V ----
#pragma unroll
        for (int k = 0; k < 8; k++) {
            uint32_t af[4];
            af[0] = __float_as_uint(Pb[(m0w + g    )*68 + 8*k + tig    ]);
            af[1] = __float_as_uint(Pb[(m0w + g + 8)*68 + 8*k + tig    ]);
            af[2] = __float_as_uint(Pb[(m0w + g    )*68 + 8*k + tig + 4]);
            af[3] = __float_as_uint(Pb[(m0w + g + 8)*68 + 8*k + tig + 4]);
#pragma unroll
            for (int n = 0; n < 8; n++) {
                uint32_t b0 = __float_as_uint(Vc[(8*k + tig    )*72 + 8*n + g]);
                uint32_t b1 = __float_as_uint(Vc[(8*k + tig + 4)*72 + 8*n + g]);
                mma8(o[n], af, b0, b1);
            }
        }
    }

    // ---- epilogue ----
    if (nch == 1) {
        const float inv0 = 1.0f / lr0, inv1 = 1.0f / lr1;
        float* obase = out + (size_t)(b*Tt + q0 + m0w)*HSd;
#pragma unroll
        for (int n = 0; n < 8; n++) {
            *(float2*)(obase + (g    )*HSd + 8*n + 2*tig) =
                make_float2(o[n][0]*inv0, o[n][1]*inv0);
            *(float2*)(obase + (g + 8)*HSd + 8*n + 2*tig) =
                make_float2(o[n][2]*inv1, o[n][3]*inv1);
        }
    } else {
        const size_t idx = (size_t)((b*NQT + qb)*MAXCH + chunk);
        float* pO = g_pO + idx*8192;
#pragma unroll
        for (int n = 0; n < 8; n++) {
            *(float2*)&pO[(m0w + g    )*64 + 8*n + 2*tig] =
                make_float2(o[n][0], o[n][1]);
            *(float2*)&pO[(m0w + g + 8)*64 + 8*n + 2*tig] =
                make_float2(o[n][2], o[n][3]);
        }
        if (tig == 0) {
            g_pm[idx*128 + m0w + g    ] = mr0;
            g_pl[idx*128 + m0w + g    ] = lr0;
            g_pm[idx*128 + m0w + g + 8] = mr1;
            g_pl[idx*128 + m0w + g + 8] = lr1;
        }
    }
#undef ISSUE
}

// ---------------------------------------------------------------------------
// Combine partials for qb >= 4. Grid (48, 8) x 512 thr — 4 column-groups per
// (b,qb) so 384 CTAs cover all 148 SMs (the 96-CTA version left 1/3 idle).
// Per-element summation order identical (ci ascending) -> bit-identical.
// ---------------------------------------------------------------------------
__global__ __launch_bounds__(512)
void combine_kernel(float* __restrict__ out)
{
    const int qb  = 4 + (blockIdx.x >> 2);
    const int cg  = blockIdx.x & 3;           // column group 0..3 (16 cols)
    const int b   = blockIdx.y;
    const int nch = (2*qb + 9) >> 3;
    const int t   = threadIdx.x;
    const int row = t >> 2;                   // 0..127
    const int oc  = cg*16 + (t & 3)*4;        // one float4 per thread
    const int base = (b*NQT + qb)*MAXCH;

    float mg = -1e30f;
    for (int i = 0; i < nch; i++)
        mg = fmaxf(mg, g_pm[(base + i)*128 + row]);

    float l = 0.f;
    float4 acc = make_float4(0.f, 0.f, 0.f, 0.f);

    for (int i = 0; i < nch; i++) {
        float w = ex2(g_pm[(base + i)*128 + row] - mg);
        l += w * g_pl[(base + i)*128 + row];
        float4 v = *(const float4*)&g_pO[(size_t)(base + i)*8192 + row*64 + oc];
        acc.x += w*v.x; acc.y += w*v.y;
        acc.z += w*v.z; acc.w += w*v.w;
    }

    const float inv = 1.0f / l;
    *(float4*)(out + (size_t)(b*Tt + qb*128 + row)*HSd + oc) =
        make_float4(acc.x*inv, acc.y*inv, acc.z*inv, acc.w*inv);
}

// ---------------------------------------------------------------------------
extern "C" void kernel_launch(void* const* d_in, const int* in_sizes, int n_in,
                              void* d_out, int out_size)
{
    const float* q_vec = (const float*)d_in[0];
    const float* k_vec = (const float*)d_in[1];
    const float* v_vec = (const float*)d_in[2];
    const int*   mask  = (const int*)  d_in[3];
    const float* Wq    = (const float*)d_in[4];
    const float* Wk    = (const float*)d_in[5];
    const float* Wv    = (const float*)d_in[6];
    float* out = (float*)d_out;

    const int proj_smem = (2*128*PPITCH + 2*32*72) * 4;               // 59392 B
    cudaFuncSetAttribute(proj_kernel,
                         cudaFuncAttributeMaxDynamicSharedMemorySize, proj_smem);
    const int attn_smem = (128*68 + 2*64*68 + 2*64*72) * 4 + 2*64*4;  // 107008 B
    cudaFuncSetAttribute(attn_kernel,
                         cudaFuncAttributeMaxDynamicSharedMemorySize, attn_smem);

    proj_kernel<<<dim3(Mrows/128, 3), 128, proj_smem>>>(q_vec, k_vec, v_vec,
                                                        Wq, Wk, Wv);
    attn_kernel<<<320, 256, attn_smem>>>(mask, out);
    combine_kernel<<<dim3(48, 8), 512>>>(out);
}

// round 16
// speedup vs baseline: 1.1717x; 1.0994x over previous
#include <cuda_runtime.h>
#include <cstdint>

#define Bb  8
#define Tt  2048
#define Cc  1024
#define HSd 64
#define Mrows (Bb*Tt)
#define NQT  16            // 128-row Q tiles per batch
#define MAXCH 4
#define APITCH 36          // proj A pitch: raw fp32, scalar frag LDS conflict-free

// Projected q/k/v (tf32-rounded fp32 bits)
__device__ float g_q[Mrows*HSd];
__device__ float g_k[Mrows*HSd];
__device__ float g_v[Mrows*HSd];
// Split-KV partials (128-row Q tiles)
__device__ float g_pO[Bb*NQT*MAXCH*128*64];
__device__ float g_pm[Bb*NQT*MAXCH*128];
__device__ float g_pl[Bb*NQT*MAXCH*128];

__device__ __forceinline__ uint32_t f2tf(float f) {
    uint32_t u;
    asm("cvt.rna.tf32.f32 %0, %1;" : "=r"(u) : "f"(f));
    return u;
}
__device__ __forceinline__ float tfv(float f) { return __uint_as_float(f2tf(f)); }
__device__ __forceinline__ float ex2(float x) {
    float r;
    asm("ex2.approx.ftz.f32 %0, %1;" : "=f"(r) : "f"(x));
    return r;
}
__device__ __forceinline__ void mma8(float* c, const uint32_t* a, uint32_t b0, uint32_t b1) {
    asm volatile(
        "mma.sync.aligned.m16n8k8.row.col.f32.tf32.tf32.f32 "
        "{%0,%1,%2,%3},{%4,%5,%6,%7},{%8,%9},{%0,%1,%2,%3};"
        : "+f"(c[0]), "+f"(c[1]), "+f"(c[2]), "+f"(c[3])
        : "r"(a[0]), "r"(a[1]), "r"(a[2]), "r"(a[3]), "r"(b0), "r"(b1));
}
__device__ __forceinline__ void cp16(uint32_t dst, const void* src) {
    asm volatile("cp.async.ca.shared.global [%0], [%1], 16;" :: "r"(dst), "l"(src));
}
__device__ __forceinline__ void cp16cg(uint32_t dst, const void* src) {
    asm volatile("cp.async.cg.shared.global [%0], [%1], 16;" :: "r"(dst), "l"(src));
}
#define CP_COMMIT() asm volatile("cp.async.commit_group;")
#define CP_WAIT0()  asm volatile("cp.async.wait_group 0;")

// ---------------------------------------------------------------------------
// Projection. CTA: 128 thr (4 warps), 128 rows x 64 cols, K-chunks of 32.
// A: raw fp32 global->smem via cp.async.cg (L1-bypassed, no reg staging),
//    pitch 36; tf32 cvt at fragment-load time (same rounding point as before
//    -> bit-identical). Scalar A-fragment LDS are conflict-free (banks
//    4g+tig distinct per instruction).
// W: LDG->reg->tfv->STS (pitch 72), unchanged from r15.
// Double-buffered, one wait_group + one barrier per chunk.
// Smem 55.3 KB -> 4 CTAs/SM (16 warps); launch_bounds caps regs at 128.
// ---------------------------------------------------------------------------
__global__ __launch_bounds__(128, 4)
void proj_kernel(const float* __restrict__ qv, const float* __restrict__ kv,
                 const float* __restrict__ vv,
                 const float* __restrict__ Wq, const float* __restrict__ Wk,
                 const float* __restrict__ Wv)
{
    extern __shared__ float sm[];
    float* As0 = sm;                          // 128*36
    float* As1 = sm + 128*APITCH;
    float* Ws0 = sm + 2*128*APITCH;           // 32*72
    float* Ws1 = sm + 2*128*APITCH + 32*72;

    const int m = blockIdx.y;
    const float* in  = (m == 0) ? qv : ((m == 1) ? kv : vv);
    float*       out = (m == 0) ? g_q : ((m == 1) ? g_k : g_v);
    const float* wt  = (m == 0) ? Wq : ((m == 1) ? Wk : Wv);

    const int tid  = threadIdx.x;
    const int wid  = tid >> 5;
    const int lane = tid & 31;
    const int g    = lane >> 2;
    const int tig  = lane & 3;
    const int row0 = blockIdx.x * 128;
    const int m0w  = wid * 32;

    const int aR = tid >> 2;          // 0..31 (+32*i)
    const int aC = (tid & 3) * 8;     // 0,8,16,24
    const int wR = tid >> 2;          // 0..31
    const int wC = (tid & 3) * 16;    // 0..48

    float4 pw[4];

#define CPA(k0, buf)                                                          \
    { _Pragma("unroll") for (int i = 0; i < 4; i++) {                         \
        const float* p = in + (size_t)(row0 + aR + 32*i)*Cc + (k0) + aC;      \
        uint32_t d = (uint32_t)__cvta_generic_to_shared(                      \
            &(buf)[(aR + 32*i)*APITCH + aC]);                                 \
        cp16cg(d, p); cp16cg(d + 16, p + 4); }                                \
      CP_COMMIT(); }

#define LDWm(k0)                                                              \
    { const float* p = wt + (size_t)((k0) + wR)*HSd + wC;                     \
      _Pragma("unroll") for (int i = 0; i < 4; i++)                           \
          pw[i] = *(const float4*)(p + 4*i); }

#define STWB(buf)                                                             \
    { _Pragma("unroll") for (int i = 0; i < 4; i++)                           \
        *(float4*)&(buf)[wR*72 + wC + 4*i] =                                  \
            make_float4(tfv(pw[i].x), tfv(pw[i].y), tfv(pw[i].z), tfv(pw[i].w)); }

    float acc[2][8][4];
#pragma unroll
    for (int mi = 0; mi < 2; mi++)
#pragma unroll
        for (int n = 0; n < 8; n++)
#pragma unroll
            for (int j = 0; j < 4; j++) acc[mi][n][j] = 0.f;

    CPA(0, As0);
    LDWm(0); STWB(Ws0);
    CP_WAIT0();
    __syncthreads();

    for (int c = 0; c < 32; c++) {
        const int cur = c & 1;
        const float* Acur = cur ? As1 : As0;
        const float* Wcur = cur ? Ws1 : Ws0;
        float* Anxt = cur ? As0 : As1;
        float* Wnxt = cur ? Ws0 : Ws1;

        if (c < 31) { CPA(32*(c+1), Anxt); LDWm(32*(c+1)); }

#pragma unroll
        for (int ks = 0; ks < 4; ks++) {
            const int kc = 8*ks + tig;
            uint32_t af0[4] = { f2tf(Acur[(m0w + g     )*APITCH + kc]),
                                f2tf(Acur[(m0w + g +  8)*APITCH + kc]),
                                f2tf(Acur[(m0w + g     )*APITCH + kc + 4]),
                                f2tf(Acur[(m0w + g +  8)*APITCH + kc + 4]) };
            uint32_t af1[4] = { f2tf(Acur[(m0w + g + 16)*APITCH + kc]),
                                f2tf(Acur[(m0w + g + 24)*APITCH + kc]),
                                f2tf(Acur[(m0w + g + 16)*APITCH + kc + 4]),
                                f2tf(Acur[(m0w + g + 24)*APITCH + kc + 4]) };
#pragma unroll
            for (int n = 0; n < 8; n++) {
                uint32_t b0 = __float_as_uint(Wcur[(8*ks + tig    )*72 + 8*n + g]);
                uint32_t b1 = __float_as_uint(Wcur[(8*ks + tig + 4)*72 + 8*n + g]);
                mma8(acc[0][n], af0, b0, b1);
                mma8(acc[1][n], af1, b0, b1);
            }
        }
        if (c < 31) STWB(Wnxt);
        CP_WAIT0();
        __syncthreads();
    }

#pragma unroll
    for (int mi = 0; mi < 2; mi++) {
        const int rb = row0 + m0w + mi*16;
#pragma unroll
        for (int n = 0; n < 8; n++) {
            *(float2*)(out + (size_t)(rb + g    )*HSd + 8*n + 2*tig) =
                make_float2(tfv(acc[mi][n][0]), tfv(acc[mi][n][1]));
            *(float2*)(out + (size_t)(rb + g + 8)*HSd + 8*n + 2*tig) =
                make_float2(tfv(acc[mi][n][2]), tfv(acc[mi][n][3]));
        }
    }
#undef CPA
#undef LDWm
#undef STWB
}

// ---------------------------------------------------------------------------
// Split-KV flash attention — EXACT r13/r15 version (best measured attn).
// ---------------------------------------------------------------------------
__global__ __launch_bounds__(256, 2)
void attn_kernel(const int* __restrict__ mask, float* __restrict__ out)
{
    extern __shared__ float asm_[];
    float* Pb  = asm_;                        // 128*68
    float* Ks0 = asm_ + 128*68;               // 64*68
    float* Ks1 = Ks0 + 64*68;
    float* Vs0 = Ks1 + 64*68;                 // 64*72
    float* Vs1 = Vs0 + 64*72;
    int*   msk = (int*)(Vs1 + 64*72);         // [2][64]

    const int i = blockIdx.x;
    const int b = i & 7;
    const int r = 39 - (i >> 3);              // heavy (large qb) first
    int qb, chunk;
    if (r < 4)       { qb = r;                        chunk = 0; }
    else if (r < 12) { int t = r - 4;  qb = 4  + (t >> 1); chunk = t & 1; }
    else if (r < 24) { int t = r - 12; qb = 8  + t/3;      chunk = t - 3*(t/3); }
    else             { int t = r - 24; qb = 12 + (t >> 2); chunk = t & 3; }
    const int nch   = (2*qb + 9) >> 3;        // 1..4
    const int kb_lo = chunk * 8;
    const int kb_hi = min(kb_lo + 8, 2*qb + 2);

    const int q0   = qb * 128;
    const int tid  = threadIdx.x;
    const int wid  = tid >> 5;
    const int lane = tid & 31;
    const int g    = lane >> 2;
    const int tig  = lane & 3;
    const int m0w  = wid * 16;

#define ISSUE(kb, buf)                                                        \
    { const float* kg = g_k + (size_t)(b*Tt + (kb)*64)*HSd;                   \
      const float* vg = g_v + (size_t)(b*Tt + (kb)*64)*HSd;                   \
      float* kd = (buf) ? Ks1 : Ks0;                                          \
      float* vd = (buf) ? Vs1 : Vs0;                                          \
      _Pragma("unroll") for (int t4 = 0; t4 < 4; t4++) {                      \
          int t = tid + 256*t4;                                               \
          int rr = t >> 4, c4 = (t & 15) << 2;                                \
          cp16((uint32_t)__cvta_generic_to_shared(&kd[rr*68 + c4]),           \
               kg + rr*HSd + c4);                                             \
          cp16((uint32_t)__cvta_generic_to_shared(&vd[rr*72 + c4]),           \
               vg + rr*HSd + c4);                                             \
      }                                                                       \
      if (tid < 16)                                                           \
          cp16((uint32_t)__cvta_generic_to_shared(&msk[(buf)*64 + tid*4]),    \
               mask + b*Tt + (kb)*64 + tid*4);                                \
      CP_COMMIT(); }

    uint32_t qf[8][4];
    const float* qbase = g_q + (size_t)(b*Tt + q0 + m0w)*HSd;
#pragma unroll
    for (int k = 0; k < 8; k++) {
        qf[k][0] = __float_as_uint(qbase[(g    )*HSd + 8*k + tig    ]);
        qf[k][1] = __float_as_uint(qbase[(g + 8)*HSd + 8*k + tig    ]);
        qf[k][2] = __float_as_uint(qbase[(g    )*HSd + 8*k + tig + 4]);
        qf[k][3] = __float_as_uint(qbase[(g + 8)*HSd + 8*k + tig + 4]);
    }

    float o[8][4];
#pragma unroll
    for (int n = 0; n < 8; n++)
#pragma unroll
        for (int j = 0; j < 4; j++) o[n][j] = 0.f;
    float mr0 = -1e30f, mr1 = -1e30f, lr0 = 0.f, lr1 = 0.f;

    const float scale2 = 0.125f * 1.4426950408889634f;
    const int row0g = q0 + m0w + g;
    const int row1g = row0g + 8;

    ISSUE(kb_lo, 0);

    for (int kb = kb_lo; kb < kb_hi; kb++) {
        const int k0 = kb * 64;
        const int cur = (kb - kb_lo) & 1;
        const float* Kc = cur ? Ks1 : Ks0;
        const float* Vc = cur ? Vs1 : Vs0;
        const int*   mc = msk + cur*64;

        CP_WAIT0();
        __syncthreads();

        if (kb + 1 < kb_hi) ISSUE(kb + 1, cur ^ 1);

        // ---- S = Q K^T ----
        float s[8][4];
#pragma unroll
        for (int n = 0; n < 8; n++)
#pragma unroll
            for (int j = 0; j < 4; j++) s[n][j] = 0.f;
#pragma unroll
        for (int k = 0; k < 8; k++) {
#pragma unroll
            for (int n = 0; n < 8; n++) {
                uint32_t b0 = __float_as_uint(Kc[(8*n + g)*68 + 8*k + tig    ]);
                uint32_t b1 = __float_as_uint(Kc[(8*n + g)*68 + 8*k + tig + 4]);
                mma8(s[n], qf[k], b0, b1);
            }
        }

        // ---- scale (log2) + causal/pad mask ----
        const bool diag = (k0 >= q0);
#pragma unroll
        for (int n = 0; n < 8; n++) {
            int cl = 8*n + 2*tig;
            int2 mm = *(const int2*)&mc[cl];
            int c0 = k0 + cl, c1 = c0 + 1;
            bool v00 = (mm.x != 0) && (!diag || c0 <= row0g);
            bool v01 = (mm.y != 0) && (!diag || c1 <= row0g);
            bool v10 = (mm.x != 0) && (!diag || c0 <= row1g);
            bool v11 = (mm.y != 0) && (!diag || c1 <= row1g);
            s[n][0] = v00 ? s[n][0]*scale2 : -1e30f;
            s[n][1] = v01 ? s[n][1]*scale2 : -1e30f;
            s[n][2] = v10 ? s[n][2]*scale2 : -1e30f;
            s[n][3] = v11 ? s[n][3]*scale2 : -1e30f;
        }

        // ---- online softmax, base-2 ----
        {
            float m0 = -1e30f, m1 = -1e30f;
#pragma unroll
            for (int n = 0; n < 8; n++) {
                m0 = fmaxf(m0, fmaxf(s[n][0], s[n][1]));
                m1 = fmaxf(m1, fmaxf(s[n][2], s[n][3]));
            }
#pragma unroll
            for (int off = 1; off < 4; off <<= 1) {
                m0 = fmaxf(m0, __shfl_xor_sync(0xffffffffu, m0, off));
                m1 = fmaxf(m1, __shfl_xor_sync(0xffffffffu, m1, off));
            }
            float mn0 = fmaxf(mr0, m0), mn1 = fmaxf(mr1, m1);
            float al0 = ex2(mr0 - mn0), al1 = ex2(mr1 - mn1);
            float ls0 = 0.f, ls1 = 0.f;
#pragma unroll
            for (int n = 0; n < 8; n++) {
                s[n][0] = ex2(s[n][0] - mn0);
                s[n][1] = ex2(s[n][1] - mn0);
                s[n][2] = ex2(s[n][2] - mn1);
                s[n][3] = ex2(s[n][3] - mn1);
                ls0 += s[n][0] + s[n][1];
                ls1 += s[n][2] + s[n][3];
            }
#pragma unroll
            for (int off = 1; off < 4; off <<= 1) {
                ls0 += __shfl_xor_sync(0xffffffffu, ls0, off);
                ls1 += __shfl_xor_sync(0xffffffffu, ls1, off);
            }
            lr0 = lr0*al0 + ls0;  mr0 = mn0;
            lr1 = lr1*al1 + ls1;  mr1 = mn1;
#pragma unroll
            for (int n = 0; n < 8; n++) {
                o[n][0] *= al0; o[n][1] *= al0;
                o[n][2] *= al1; o[n][3] *= al1;
            }
        }

        // ---- P (tf32) into own rows of Pb; warp-private ----
#pragma unroll
        for (int n = 0; n < 8; n++) {
            float2 p0 = make_float2(tfv(s[n][0]), tfv(s[n][1]));
            float2 p1 = make_float2(tfv(s[n][2]), tfv(s[n][3]));
            *(float2*)&Pb[(m0w + g    )*68 + 8*n + 2*tig] = p0;
            *(float2*)&Pb[(m0w + g + 8)*68 + 8*n + 2*tig] = p1;
        }
        __syncwarp();

        // ---- O += P V ----
#pragma unroll
        for (int k = 0; k < 8; k++) {
            uint32_t af[4];
            af[0] = __float_as_uint(Pb[(m0w + g    )*68 + 8*k + tig    ]);
            af[1] = __float_as_uint(Pb[(m0w + g + 8)*68 + 8*k + tig    ]);
            af[2] = __float_as_uint(Pb[(m0w + g    )*68 + 8*k + tig + 4]);
            af[3] = __float_as_uint(Pb[(m0w + g + 8)*68 + 8*k + tig + 4]);
#pragma unroll
            for (int n = 0; n < 8; n++) {
                uint32_t b0 = __float_as_uint(Vc[(8*k + tig    )*72 + 8*n + g]);
                uint32_t b1 = __float_as_uint(Vc[(8*k + tig + 4)*72 + 8*n + g]);
                mma8(o[n], af, b0, b1);
            }
        }
    }

    // ---- epilogue ----
    if (nch == 1) {
        const float inv0 = 1.0f / lr0, inv1 = 1.0f / lr1;
        float* obase = out + (size_t)(b*Tt + q0 + m0w)*HSd;
#pragma unroll
        for (int n = 0; n < 8; n++) {
            *(float2*)(obase + (g    )*HSd + 8*n + 2*tig) =
                make_float2(o[n][0]*inv0, o[n][1]*inv0);
            *(float2*)(obase + (g + 8)*HSd + 8*n + 2*tig) =
                make_float2(o[n][2]*inv1, o[n][3]*inv1);
        }
    } else {
        const size_t idx = (size_t)((b*NQT + qb)*MAXCH + chunk);
        float* pO = g_pO + idx*8192;
#pragma unroll
        for (int n = 0; n < 8; n++) {
            *(float2*)&pO[(m0w + g    )*64 + 8*n + 2*tig] =
                make_float2(o[n][0], o[n][1]);
            *(float2*)&pO[(m0w + g + 8)*64 + 8*n + 2*tig] =
                make_float2(o[n][2], o[n][3]);
        }
        if (tig == 0) {
            g_pm[idx*128 + m0w + g    ] = mr0;
            g_pl[idx*128 + m0w + g    ] = lr0;
            g_pm[idx*128 + m0w + g + 8] = mr1;
            g_pl[idx*128 + m0w + g + 8] = lr1;
        }
    }
#undef ISSUE
}

// ---------------------------------------------------------------------------
// Combine partials for qb >= 4. Grid (48, 8) x 512 thr (r15 verbatim).
// ---------------------------------------------------------------------------
__global__ __launch_bounds__(512)
void combine_kernel(float* __restrict__ out)
{
    const int qb  = 4 + (blockIdx.x >> 2);
    const int cg  = blockIdx.x & 3;           // column group 0..3 (16 cols)
    const int b   = blockIdx.y;
    const int nch = (2*qb + 9) >> 3;
    const int t   = threadIdx.x;
    const int row = t >> 2;                   // 0..127
    const int oc  = cg*16 + (t & 3)*4;        // one float4 per thread
    const int base = (b*NQT + qb)*MAXCH;

    float mg = -1e30f;
    for (int i = 0; i < nch; i++)
        mg = fmaxf(mg, g_pm[(base + i)*128 + row]);

    float l = 0.f;
    float4 acc = make_float4(0.f, 0.f, 0.f, 0.f);

    for (int i = 0; i < nch; i++) {
        float w = ex2(g_pm[(base + i)*128 + row] - mg);
        l += w * g_pl[(base + i)*128 + row];
        float4 v = *(const float4*)&g_pO[(size_t)(base + i)*8192 + row*64 + oc];
        acc.x += w*v.x; acc.y += w*v.y;
        acc.z += w*v.z; acc.w += w*v.w;
    }

    const float inv = 1.0f / l;
    *(float4*)(out + (size_t)(b*Tt + qb*128 + row)*HSd + oc) =
        make_float4(acc.x*inv, acc.y*inv, acc.z*inv, acc.w*inv);
}

// ---------------------------------------------------------------------------
extern "C" void kernel_launch(void* const* d_in, const int* in_sizes, int n_in,
                              void* d_out, int out_size)
{
    const float* q_vec = (const float*)d_in[0];
    const float* k_vec = (const float*)d_in[1];
    const float* v_vec = (const float*)d_in[2];
    const int*   mask  = (const int*)  d_in[3];
    const float* Wq    = (const float*)d_in[4];
    const float* Wk    = (const float*)d_in[5];
    const float* Wv    = (const float*)d_in[6];
    float* out = (float*)d_out;

    const int proj_smem = (2*128*APITCH + 2*32*72) * 4;               // 55296 B
    cudaFuncSetAttribute(proj_kernel,
                         cudaFuncAttributeMaxDynamicSharedMemorySize, proj_smem);
    const int attn_smem = (128*68 + 2*64*68 + 2*64*72) * 4 + 2*64*4;  // 107008 B
    cudaFuncSetAttribute(attn_kernel,
                         cudaFuncAttributeMaxDynamicSharedMemorySize, attn_smem);

    proj_kernel<<<dim3(Mrows/128, 3), 128, proj_smem>>>(q_vec, k_vec, v_vec,
                                                        Wq, Wk, Wv);
    attn_kernel<<<320, 256, attn_smem>>>(mask, out);
    combine_kernel<<<dim3(48, 8), 512>>>(out);
}